// round 4
// baseline (speedup 1.0000x reference)
#include <cuda_runtime.h>
#include <math.h>
#include <stdint.h>

#define B_BATCH 8
#define N_SEQ   1024
#define HID     4096
#define HALF_K  2048
#define MROWS   (B_BATCH * N_SEQ)   /* 8192 */
#define THRESH_F 0.85f

// ---------------- scratch (static __device__, no allocs) ----------------
__device__ float    g_P[(size_t)MROWS * HALF_K];      // gelu(GEMM) out (tf32-rounded), reused as H
__device__ float    g_NORM[(size_t)MROWS * HALF_K];   // LN + L2-normalized rows (tf32-rounded)
__device__ float    g_RND[(size_t)MROWS * HID];       // tf32(seg)
__device__ float    g_SEGI[(size_t)MROWS * HID];      // tf32(seg * imp)
__device__ float    g_WsimT[(size_t)HALF_K * HID];    // tf32-rounded transposed weights
__device__ float    g_Wd1T[(size_t)HALF_K * HID];
__device__ float    g_Wd2T[(size_t)HID * HALF_K];
__device__ unsigned g_COND[B_BATCH * N_SEQ * (N_SEQ / 32)];
__device__ float    g_KEPT[MROWS];

// ---------------- helpers ----------------
__device__ __forceinline__ float f2tf_f(float x) {
    unsigned u; asm("cvt.rna.tf32.f32 %0, %1;" : "=r"(u) : "f"(x));
    return __uint_as_float(u);
}
__device__ __forceinline__ float gelu_exact(float x) { return x * normcdff(x); }

__device__ __forceinline__ uint32_t smem_u32(const void* p) {
    uint32_t a;
    asm("{ .reg .u64 t; cvta.to.shared.u64 t, %1; cvt.u32.u64 %0, t; }" : "=r"(a) : "l"(p));
    return a;
}
__device__ __forceinline__ void cp_async16(void* dst, const void* src) {
    uint32_t d = smem_u32(dst);
    asm volatile("cp.async.cg.shared.global [%0], [%1], 16;" :: "r"(d), "l"(src) : "memory");
}
#define CP_COMMIT() asm volatile("cp.async.commit_group;" ::: "memory")
#define CP_WAIT1()  asm volatile("cp.async.wait_group 1;" ::: "memory")

// ---------------- TF32 mma.sync GEMM (NT): C[M,N] = A[M,K] @ B^T, B rows [N,K] ----------------
// Inputs must already be tf32-rounded. CTA 128x256, BK=32, 3-stage cp.async,
// 8 warps in 2(M) x 4(N), warp tile 64x64. No cvt / no scaling in the mainloop.
enum { EPI_GELU = 0, EPI_BIAS_MASK = 1, EPI_PACK = 2 };

constexpr int BM = 128, BN = 256, BK = 32, STAGES = 3;
constexpr int RSTR = 36;                       // smem row stride in words (32 + 4 pad)
constexpr int A_STAGE_W = BM * RSTR;
constexpr int B_STAGE_W = BN * RSTR;
constexpr int SMEM_WORDS = STAGES * (A_STAGE_W + B_STAGE_W);
constexpr int SMEM_BYTES = SMEM_WORDS * 4;     // 165888 B

template <int EPI>
__global__ __launch_bounds__(256, 1)
void gemm_sync(const float* __restrict__ A, const float* __restrict__ Bm,
               void* __restrict__ Cv, int M, int Ncols, int K,
               const float* __restrict__ bias,
               const float* __restrict__ rowmask, const float* __restrict__ imp,
               long long sA, long long sB, long long sC)
{
    extern __shared__ float sm[];
    float* smA = sm;                           // [STAGES][BM][RSTR]
    float* smB = sm + STAGES * A_STAGE_W;      // [STAGES][BN][RSTR]

    const int tid = threadIdx.x, lane = tid & 31, wid = tid >> 5;
    const int wm = wid & 1, wn = wid >> 1;     // 2 x 4 warp grid
    const int g = lane >> 2, t = lane & 3;
    const int z = blockIdx.z;
    const float* Az = A + (size_t)z * sA;
    const float* Bz = Bm + (size_t)z * sB;
    const int row0 = blockIdx.y * BM;
    const int col0 = blockIdx.x * BN;
    const int KT = K / BK;

    auto load_stage = [&](int kt, int s) {
        float* a = smA + s * A_STAGE_W;
        const float* ag = Az + (size_t)row0 * K + (size_t)kt * BK;
#pragma unroll
        for (int i = 0; i < 4; i++) {
            int idx = tid + i * 256; int r = idx >> 3, c = idx & 7;
            cp_async16(a + r * RSTR + c * 4, ag + (size_t)r * K + c * 4);
        }
        float* b = smB + s * B_STAGE_W;
        const float* bg = Bz + (size_t)col0 * K + (size_t)kt * BK;
#pragma unroll
        for (int i = 0; i < 8; i++) {
            int idx = tid + i * 256; int r = idx >> 3, c = idx & 7;
            cp_async16(b + r * RSTR + c * 4, bg + (size_t)r * K + c * 4);
        }
    };

    load_stage(0, 0); CP_COMMIT();
    load_stage(1, 1); CP_COMMIT();

    float acc[4][8][4] = {};

    // per-warp smem fragment bases (constant across k tiles)
    const int aBase = (wm * 64 + g) * RSTR + t;
    const int bBase = (wn * 64 + g) * RSTR + t;

    for (int kt = 0; kt < KT; kt++) {
        const int s = kt % 3;
        CP_WAIT1();
        __syncthreads();
        if (kt + 2 < KT) load_stage(kt + 2, (kt + 2) % 3);
        CP_COMMIT();

        const float* a = smA + s * A_STAGE_W + aBase;
        const float* b = smB + s * B_STAGE_W + bBase;
#pragma unroll
        for (int ks = 0; ks < 4; ks++) {
            const int k0 = ks * 8;
            unsigned af[4][4], bf[8][2];
#pragma unroll
            for (int mi = 0; mi < 4; mi++) {
                const float* ap = a + mi * 16 * RSTR;
                af[mi][0] = __float_as_uint(ap[k0]);
                af[mi][1] = __float_as_uint(ap[8 * RSTR + k0]);
                af[mi][2] = __float_as_uint(ap[k0 + 4]);
                af[mi][3] = __float_as_uint(ap[8 * RSTR + k0 + 4]);
            }
#pragma unroll
            for (int ni = 0; ni < 8; ni++) {
                const float* bp = b + ni * 8 * RSTR;
                bf[ni][0] = __float_as_uint(bp[k0]);
                bf[ni][1] = __float_as_uint(bp[k0 + 4]);
            }
#pragma unroll
            for (int mi = 0; mi < 4; mi++)
#pragma unroll
                for (int ni = 0; ni < 8; ni++) {
                    asm volatile(
                        "mma.sync.aligned.m16n8k8.row.col.f32.tf32.tf32.f32 "
                        "{%0,%1,%2,%3}, {%4,%5,%6,%7}, {%8,%9}, {%0,%1,%2,%3};\n"
                        : "+f"(acc[mi][ni][0]), "+f"(acc[mi][ni][1]),
                          "+f"(acc[mi][ni][2]), "+f"(acc[mi][ni][3])
                        : "r"(af[mi][0]), "r"(af[mi][1]), "r"(af[mi][2]), "r"(af[mi][3]),
                          "r"(bf[ni][0]), "r"(bf[ni][1]));
                }
        }
    }

    // ---------------- epilogue ----------------
    if (EPI == EPI_PACK) {
        unsigned* cond = (unsigned*)Cv + (size_t)z * sC;
        const float* impb = imp + (size_t)z * N_SEQ;
        const int wstride = Ncols >> 5;
        const int cb = col0 + wn * 64;
        float impj[8][2];
#pragma unroll
        for (int ni = 0; ni < 8; ni++) {
            impj[ni][0] = impb[cb + ni * 8 + 2 * t];
            impj[ni][1] = impb[cb + ni * 8 + 2 * t + 1];
        }
        float impi[4][2];
#pragma unroll
        for (int mi = 0; mi < 4; mi++)
#pragma unroll
            for (int h = 0; h < 2; h++)
                impi[mi][h] = impb[row0 + wm * 64 + mi * 16 + g + 8 * h];

#pragma unroll
        for (int mi = 0; mi < 4; mi++) {
#pragma unroll
            for (int h = 0; h < 2; h++) {
                unsigned w0 = 0, w1 = 0;
#pragma unroll
                for (int ni = 0; ni < 8; ni++) {
                    float v0 = acc[mi][ni][h * 2 + 0];
                    float v1 = acc[mi][ni][h * 2 + 1];
                    unsigned b0 = (v0 > THRESH_F && impj[ni][0] >= impi[mi][h]) ? 1u : 0u;
                    unsigned b1 = (v1 > THRESH_F && impj[ni][1] >= impi[mi][h]) ? 1u : 0u;
                    unsigned bits = (b0 << ((ni & 3) * 8 + 2 * t)) | (b1 << ((ni & 3) * 8 + 2 * t + 1));
                    if (ni < 4) w0 |= bits; else w1 |= bits;
                }
                w0 |= __shfl_xor_sync(0xffffffffu, w0, 1);
                w0 |= __shfl_xor_sync(0xffffffffu, w0, 2);
                w1 |= __shfl_xor_sync(0xffffffffu, w1, 1);
                w1 |= __shfl_xor_sync(0xffffffffu, w1, 2);
                if (t == 0) {
                    int r = row0 + wm * 64 + mi * 16 + g + 8 * h;
                    cond[(size_t)r * wstride + (cb >> 5)    ] = w0;
                    cond[(size_t)r * wstride + (cb >> 5) + 1] = w1;
                }
            }
        }
    } else {
        float* C = (float*)Cv + (size_t)z * sC;
        float2 bv[8];
#pragma unroll
        for (int ni = 0; ni < 8; ni++)
            bv[ni] = *(const float2*)(bias + col0 + wn * 64 + ni * 8 + 2 * t);
        float mkr[4][2];
#pragma unroll
        for (int mi = 0; mi < 4; mi++)
#pragma unroll
            for (int h = 0; h < 2; h++)
                mkr[mi][h] = (EPI == EPI_BIAS_MASK)
                           ? rowmask[row0 + wm * 64 + mi * 16 + g + 8 * h] : 1.0f;

#pragma unroll
        for (int mi = 0; mi < 4; mi++) {
#pragma unroll
            for (int ni = 0; ni < 8; ni++) {
                const int c = col0 + wn * 64 + ni * 8 + 2 * t;
#pragma unroll
                for (int h = 0; h < 2; h++) {
                    const int r = row0 + wm * 64 + mi * 16 + g + 8 * h;
                    float v0 = acc[mi][ni][h * 2 + 0] + bv[ni].x;
                    float v1 = acc[mi][ni][h * 2 + 1] + bv[ni].y;
                    if (EPI == EPI_GELU) {
                        // round to tf32 at write: consumers are tf32 GEMMs / LN
                        v0 = f2tf_f(gelu_exact(v0)); v1 = f2tf_f(gelu_exact(v1));
                    } else {
                        v0 *= mkr[mi][h]; v1 *= mkr[mi][h];
                    }
                    *(float2*)(C + (size_t)r * Ncols + c) = make_float2(v0, v1);
                }
            }
        }
    }
}

// ---------------- prep: RND = tf32(seg), SEGI = tf32(seg*imp) ----------------
__global__ __launch_bounds__(256)
void prep_seg(const float4* __restrict__ seg, const float* __restrict__ imp,
              float4* __restrict__ rnd, float4* __restrict__ segi)
{
    size_t idx = (size_t)blockIdx.x * 256 + threadIdx.x;   // over MROWS*HID/4
    float4 v = seg[idx];
    float s = imp[idx >> 10];                              // HID/4 = 1024 float4 per row
    float4 r, w;
    r.x = f2tf_f(v.x); r.y = f2tf_f(v.y); r.z = f2tf_f(v.z); r.w = f2tf_f(v.w);
    w.x = f2tf_f(v.x * s); w.y = f2tf_f(v.y * s); w.z = f2tf_f(v.z * s); w.w = f2tf_f(v.w * s);
    rnd[idx] = r;
    segi[idx] = w;
}

// ---------------- 32x32 tiled transpose with tf32 rounding ----------------
__global__ void transpose32(const float* __restrict__ in, float* __restrict__ out,
                            int R, int C)
{
    __shared__ float t[32][33];
    const int c0 = blockIdx.x * 32, r0 = blockIdx.y * 32;
#pragma unroll
    for (int j = 0; j < 32; j += 8)
        t[threadIdx.y + j][threadIdx.x] =
            f2tf_f(in[(size_t)(r0 + threadIdx.y + j) * C + c0 + threadIdx.x]);
    __syncthreads();
#pragma unroll
    for (int j = 0; j < 32; j += 8)
        out[(size_t)(c0 + threadIdx.y + j) * R + r0 + threadIdx.x] = t[threadIdx.x][threadIdx.y + j];
}

// ---------------- LayerNorm + L2 normalize (tf32-rounded output) ----------------
__global__ __launch_bounds__(256)
void ln_normalize(const float* __restrict__ P, const float* __restrict__ gw,
                  const float* __restrict__ bw, float* __restrict__ O)
{
    const long long row = blockIdx.x;
    const float4* p4 = (const float4*)(P + row * HALF_K);
    float4*       o4 = (float4*)(O + row * HALF_K);
    const int tid = threadIdx.x, lane = tid & 31, warp = tid >> 5;

    float4 x0 = p4[tid], x1 = p4[tid + 256];
    float s1 = x0.x + x0.y + x0.z + x0.w + x1.x + x1.y + x1.z + x1.w;
    float s2 = x0.x * x0.x + x0.y * x0.y + x0.z * x0.z + x0.w * x0.w
             + x1.x * x1.x + x1.y * x1.y + x1.z * x1.z + x1.w * x1.w;

    __shared__ float shA[8], shB[8];
#pragma unroll
    for (int o = 16; o > 0; o >>= 1) {
        s1 += __shfl_down_sync(0xffffffffu, s1, o);
        s2 += __shfl_down_sync(0xffffffffu, s2, o);
    }
    if (lane == 0) { shA[warp] = s1; shB[warp] = s2; }
    __syncthreads();
    if (tid == 0) {
        float a = 0.f, b = 0.f;
        for (int w = 0; w < 8; w++) { a += shA[w]; b += shB[w]; }
        shA[0] = a; shB[0] = b;
    }
    __syncthreads();
    const float mu   = shA[0] * (1.0f / HALF_K);
    const float var  = shB[0] * (1.0f / HALF_K) - mu * mu;
    const float rstd = rsqrtf(var + 1e-5f);

    float4 gg0 = ((const float4*)gw)[tid], gg1 = ((const float4*)gw)[tid + 256];
    float4 bb0 = ((const float4*)bw)[tid], bb1 = ((const float4*)bw)[tid + 256];

    float4 y0, y1;
    y0.x = (x0.x - mu) * rstd * gg0.x + bb0.x;
    y0.y = (x0.y - mu) * rstd * gg0.y + bb0.y;
    y0.z = (x0.z - mu) * rstd * gg0.z + bb0.z;
    y0.w = (x0.w - mu) * rstd * gg0.w + bb0.w;
    y1.x = (x1.x - mu) * rstd * gg1.x + bb1.x;
    y1.y = (x1.y - mu) * rstd * gg1.y + bb1.y;
    y1.z = (x1.z - mu) * rstd * gg1.z + bb1.z;
    y1.w = (x1.w - mu) * rstd * gg1.w + bb1.w;

    float s3 = y0.x * y0.x + y0.y * y0.y + y0.z * y0.z + y0.w * y0.w
             + y1.x * y1.x + y1.y * y1.y + y1.z * y1.z + y1.w * y1.w;

    __syncthreads();
#pragma unroll
    for (int o = 16; o > 0; o >>= 1) s3 += __shfl_down_sync(0xffffffffu, s3, o);
    if (lane == 0) shA[warp] = s3;
    __syncthreads();
    if (tid == 0) {
        float a = 0.f;
        for (int w = 0; w < 8; w++) a += shA[w];
        shA[0] = a;
    }
    __syncthreads();
    const float inv = 1.0f / (sqrtf(shA[0]) + 1e-8f);

    y0.x = f2tf_f(y0.x * inv); y0.y = f2tf_f(y0.y * inv);
    y0.z = f2tf_f(y0.z * inv); y0.w = f2tf_f(y0.w * inv);
    y1.x = f2tf_f(y1.x * inv); y1.y = f2tf_f(y1.y * inv);
    y1.z = f2tf_f(y1.z * inv); y1.w = f2tf_f(y1.w * inv);
    o4[tid] = y0; o4[tid + 256] = y1;
}

// ---------------- sequential greedy keep (1 warp per batch, depth-16 prefetch) ----------------
__global__ void greedy_keep(const unsigned* __restrict__ cond,
                            float* __restrict__ kept1, float* __restrict__ kept2)
{
    const int warp = threadIdx.x >> 5, lane = threadIdx.x & 31;
    const int b = warp;  // 8 warps = 8 batches
    const unsigned* cw = cond + b * 1024 * 32;

    unsigned ring[16];
#pragma unroll
    for (int d = 0; d < 16; d++) ring[d] = cw[d * 32 + lane];

    unsigned Kr = 0;
    for (int ib = 0; ib < 1024; ib += 16) {
#pragma unroll
        for (int d = 0; d < 16; d++) {
            const int i = ib + d;
            unsigned word = ring[d];
            ring[d] = (i + 16 < 1024) ? cw[(i + 16) * 32 + lane] : 0u;  // prefetch
            const int wHi = i >> 5, bp = i & 31;
            unsigned m = (lane < wHi) ? 0xffffffffu
                       : ((lane == wHi) ? (bp ? ((1u << bp) - 1u) : 0u) : 0u);
            bool sup = __any_sync(0xffffffffu, (word & m & Kr) != 0u);
            if (!sup && lane == wHi) Kr |= (1u << bp);
        }
    }
#pragma unroll
    for (int bpos = 0; bpos < 32; bpos++) {
        float v = (float)((Kr >> bpos) & 1u);
        int j = lane * 32 + bpos;
        kept1[b * 1024 + j] = v;
        kept2[b * 1024 + j] = v;
    }
}

// ---------------- launch ----------------
extern "C" void kernel_launch(void* const* d_in, const int* in_sizes, int n_in,
                              void* d_out, int out_size)
{
    const float* seg  = (const float*)d_in[0];
    const float* imp  = (const float*)d_in[1];
    const float* Wsim = (const float*)d_in[2];
    const float* bsim = (const float*)d_in[3];
    const float* lng  = (const float*)d_in[4];
    const float* lnb  = (const float*)d_in[5];
    const float* Wd1  = (const float*)d_in[6];
    const float* bd1  = (const float*)d_in[7];
    const float* Wd2  = (const float*)d_in[8];
    const float* bd2  = (const float*)d_in[9];
    float* out = (float*)d_out;

    float *P, *NORM, *RND, *SEGI, *WsimT, *Wd1T, *Wd2T, *KEPT; unsigned* COND;
    cudaGetSymbolAddress((void**)&P,     g_P);
    cudaGetSymbolAddress((void**)&NORM,  g_NORM);
    cudaGetSymbolAddress((void**)&RND,   g_RND);
    cudaGetSymbolAddress((void**)&SEGI,  g_SEGI);
    cudaGetSymbolAddress((void**)&WsimT, g_WsimT);
    cudaGetSymbolAddress((void**)&Wd1T,  g_Wd1T);
    cudaGetSymbolAddress((void**)&Wd2T,  g_Wd2T);
    cudaGetSymbolAddress((void**)&COND,  g_COND);
    cudaGetSymbolAddress((void**)&KEPT,  g_KEPT);

    cudaFuncSetAttribute(gemm_sync<EPI_GELU>,      cudaFuncAttributeMaxDynamicSharedMemorySize, SMEM_BYTES);
    cudaFuncSetAttribute(gemm_sync<EPI_BIAS_MASK>, cudaFuncAttributeMaxDynamicSharedMemorySize, SMEM_BYTES);
    cudaFuncSetAttribute(gemm_sync<EPI_PACK>,      cudaFuncAttributeMaxDynamicSharedMemorySize, SMEM_BYTES);

    const dim3 tblk(32, 8);

    // pre-rounded activations + weight transposes (tf32)
    prep_seg<<<(MROWS * (HID / 4)) / 256, 256>>>((const float4*)seg, imp,
                                                 (float4*)RND, (float4*)SEGI);
    transpose32<<<dim3(HALF_K / 32, HID / 32), tblk>>>(Wsim, WsimT, HID, HALF_K);
    transpose32<<<dim3(HALF_K / 32, HID / 32), tblk>>>(Wd1,  Wd1T,  HID, HALF_K);
    transpose32<<<dim3(HID / 32, HALF_K / 32), tblk>>>(Wd2,  Wd2T,  HALF_K, HID);

    // 1) P = tf32(gelu(RND @ W_sim + b_sim))
    gemm_sync<EPI_GELU><<<dim3(HALF_K / BN, MROWS / BM, 1), 256, SMEM_BYTES>>>(
        RND, WsimT, P, MROWS, HALF_K, HID, bsim, nullptr, nullptr, 0, 0, 0);

    // 2) NORM = tf32(l2norm(layernorm(P)))
    ln_normalize<<<MROWS, 256>>>(P, lng, lnb, NORM);

    // 3) sim = NORM @ NORM^T with fused threshold/importance bit-pack
    gemm_sync<EPI_PACK><<<dim3(N_SEQ / BN, N_SEQ / BM, B_BATCH), 256, SMEM_BYTES>>>(
        NORM, NORM, COND, N_SEQ, N_SEQ, HALF_K, nullptr, nullptr, imp,
        (long long)N_SEQ * HALF_K, (long long)N_SEQ * HALF_K, (long long)N_SEQ * (N_SEQ / 32));

    // 4) sequential greedy keep -> KEPT + kept_mask output region
    greedy_keep<<<1, 256>>>(COND, KEPT, out + (size_t)MROWS * HID);

    // 5) H = tf32(gelu(SEGI @ W_d1 + b_d1))   (reuse P as H)
    gemm_sync<EPI_GELU><<<dim3(HALF_K / BN, MROWS / BM, 1), 256, SMEM_BYTES>>>(
        SEGI, Wd1T, P, MROWS, HALF_K, HID, bd1, nullptr, nullptr, 0, 0, 0);

    // 6) out = (H @ W_d2 + b_d2) * kept
    gemm_sync<EPI_BIAS_MASK><<<dim3(HID / BN, MROWS / BM, 1), 256, SMEM_BYTES>>>(
        P, Wd2T, out, MROWS, HID, HALF_K, bd2, KEPT, nullptr, 0, 0, 0);
}

// round 5
// speedup vs baseline: 1.3472x; 1.3472x over previous
#include <cuda_runtime.h>
#include <math.h>
#include <stdint.h>

#define B_BATCH 8
#define N_SEQ   1024
#define HID     4096
#define HALF_K  2048
#define MROWS   (B_BATCH * N_SEQ)   /* 8192 */
#define THRESH_F 0.85f

// ---------------- scratch (static __device__, no allocs) ----------------
__device__ float    g_P[(size_t)MROWS * HALF_K];      // gelu(GEMM) out (tf32-rounded), reused as H
__device__ float    g_NORM[(size_t)MROWS * HALF_K];   // LN + L2-normalized rows (tf32-rounded)
__device__ float    g_RND[(size_t)MROWS * HID];       // tf32(seg)
__device__ float    g_SEGI[(size_t)MROWS * HID];      // tf32(seg * imp)
__device__ float    g_WsimT[(size_t)HALF_K * HID];    // tf32-rounded transposed weights
__device__ float    g_Wd1T[(size_t)HALF_K * HID];
__device__ float    g_Wd2T[(size_t)HID * HALF_K];
__device__ unsigned g_COND[B_BATCH * N_SEQ * (N_SEQ / 32)];
__device__ float    g_KEPT[MROWS];

// ---------------- helpers ----------------
__device__ __forceinline__ float f2tf_f(float x) {
    unsigned u; asm("cvt.rna.tf32.f32 %0, %1;" : "=r"(u) : "f"(x));
    return __uint_as_float(u);
}
__device__ __forceinline__ float gelu_exact(float x) { return x * normcdff(x); }

__device__ __forceinline__ uint32_t smem_u32(const void* p) {
    uint32_t a;
    asm("{ .reg .u64 t; cvta.to.shared.u64 t, %1; cvt.u32.u64 %0, t; }" : "=r"(a) : "l"(p));
    return a;
}
__device__ __forceinline__ void cp_async16(void* dst, const void* src) {
    uint32_t d = smem_u32(dst);
    asm volatile("cp.async.cg.shared.global [%0], [%1], 16;" :: "r"(d), "l"(src) : "memory");
}
#define CP_COMMIT() asm volatile("cp.async.commit_group;" ::: "memory")
#define CP_WAIT1()  asm volatile("cp.async.wait_group 1;" ::: "memory")

// ---------------- TF32 mma.sync GEMM (NT): C[M,N] = A[M,K] @ B^T, B rows [N,K] ----------------
// Inputs must already be tf32-rounded. CTA 128x256, BK=32, 3-stage cp.async,
// 512 threads: 16 warps in 4(M) x 4(N), warp tile 32x64.
enum { EPI_GELU = 0, EPI_BIAS_MASK = 1, EPI_PACK = 2 };

constexpr int BM = 128, BN = 256, BK = 32, STAGES = 3;
constexpr int NTHREADS = 512;
constexpr int RSTR = 36;                       // smem row stride in words (32 + 4 pad)
constexpr int A_STAGE_W = BM * RSTR;
constexpr int B_STAGE_W = BN * RSTR;
constexpr int SMEM_WORDS = STAGES * (A_STAGE_W + B_STAGE_W);
constexpr int SMEM_BYTES = SMEM_WORDS * 4;     // 165888 B

template <int EPI>
__global__ __launch_bounds__(NTHREADS, 1)
void gemm_sync(const float* __restrict__ A, const float* __restrict__ Bm,
               void* __restrict__ Cv, int M, int Ncols, int K,
               const float* __restrict__ bias,
               const float* __restrict__ rowmask, const float* __restrict__ imp,
               long long sA, long long sB, long long sC)
{
    extern __shared__ float sm[];
    float* smA = sm;                           // [STAGES][BM][RSTR]
    float* smB = sm + STAGES * A_STAGE_W;      // [STAGES][BN][RSTR]

    const int tid = threadIdx.x, lane = tid & 31, wid = tid >> 5;
    const int wm = wid & 3, wn = wid >> 2;     // 4 x 4 warp grid
    const int g = lane >> 2, t = lane & 3;
    const int z = blockIdx.z;
    const float* Az = A + (size_t)z * sA;
    const float* Bz = Bm + (size_t)z * sB;
    const int row0 = blockIdx.y * BM;
    const int col0 = blockIdx.x * BN;
    const int KT = K / BK;

    auto load_stage = [&](int kt, int s) {
        float* a = smA + s * A_STAGE_W;
        const float* ag = Az + (size_t)row0 * K + (size_t)kt * BK;
#pragma unroll
        for (int i = 0; i < 2; i++) {
            int idx = tid + i * NTHREADS; int r = idx >> 3, c = idx & 7;
            cp_async16(a + r * RSTR + c * 4, ag + (size_t)r * K + c * 4);
        }
        float* b = smB + s * B_STAGE_W;
        const float* bg = Bz + (size_t)col0 * K + (size_t)kt * BK;
#pragma unroll
        for (int i = 0; i < 4; i++) {
            int idx = tid + i * NTHREADS; int r = idx >> 3, c = idx & 7;
            cp_async16(b + r * RSTR + c * 4, bg + (size_t)r * K + c * 4);
        }
    };

    load_stage(0, 0); CP_COMMIT();
    load_stage(1, 1); CP_COMMIT();

    float acc[2][8][4] = {};

    // per-warp smem fragment bases (constant across k tiles)
    const int aBase = (wm * 32 + g) * RSTR + t;
    const int bBase = (wn * 64 + g) * RSTR + t;

    for (int kt = 0; kt < KT; kt++) {
        const int s = kt % 3;
        CP_WAIT1();
        __syncthreads();
        if (kt + 2 < KT) load_stage(kt + 2, (kt + 2) % 3);
        CP_COMMIT();

        const float* a = smA + s * A_STAGE_W + aBase;
        const float* b = smB + s * B_STAGE_W + bBase;
#pragma unroll
        for (int ks = 0; ks < 4; ks++) {
            const int k0 = ks * 8;
            unsigned af[2][4], bf[8][2];
#pragma unroll
            for (int mi = 0; mi < 2; mi++) {
                const float* ap = a + mi * 16 * RSTR;
                af[mi][0] = __float_as_uint(ap[k0]);
                af[mi][1] = __float_as_uint(ap[8 * RSTR + k0]);
                af[mi][2] = __float_as_uint(ap[k0 + 4]);
                af[mi][3] = __float_as_uint(ap[8 * RSTR + k0 + 4]);
            }
#pragma unroll
            for (int ni = 0; ni < 8; ni++) {
                const float* bp = b + ni * 8 * RSTR;
                bf[ni][0] = __float_as_uint(bp[k0]);
                bf[ni][1] = __float_as_uint(bp[k0 + 4]);
            }
#pragma unroll
            for (int mi = 0; mi < 2; mi++)
#pragma unroll
                for (int ni = 0; ni < 8; ni++) {
                    asm volatile(
                        "mma.sync.aligned.m16n8k8.row.col.f32.tf32.tf32.f32 "
                        "{%0,%1,%2,%3}, {%4,%5,%6,%7}, {%8,%9}, {%0,%1,%2,%3};\n"
                        : "+f"(acc[mi][ni][0]), "+f"(acc[mi][ni][1]),
                          "+f"(acc[mi][ni][2]), "+f"(acc[mi][ni][3])
                        : "r"(af[mi][0]), "r"(af[mi][1]), "r"(af[mi][2]), "r"(af[mi][3]),
                          "r"(bf[ni][0]), "r"(bf[ni][1]));
                }
        }
    }

    // ---------------- epilogue ----------------
    if (EPI == EPI_PACK) {
        unsigned* cond = (unsigned*)Cv + (size_t)z * sC;
        const float* impb = imp + (size_t)z * N_SEQ;
        const int wstride = Ncols >> 5;
        const int cb = col0 + wn * 64;
        float impj[8][2];
#pragma unroll
        for (int ni = 0; ni < 8; ni++) {
            impj[ni][0] = impb[cb + ni * 8 + 2 * t];
            impj[ni][1] = impb[cb + ni * 8 + 2 * t + 1];
        }
        float impi[2][2];
#pragma unroll
        for (int mi = 0; mi < 2; mi++)
#pragma unroll
            for (int h = 0; h < 2; h++)
                impi[mi][h] = impb[row0 + wm * 32 + mi * 16 + g + 8 * h];

#pragma unroll
        for (int mi = 0; mi < 2; mi++) {
#pragma unroll
            for (int h = 0; h < 2; h++) {
                unsigned w0 = 0, w1 = 0;
#pragma unroll
                for (int ni = 0; ni < 8; ni++) {
                    float v0 = acc[mi][ni][h * 2 + 0];
                    float v1 = acc[mi][ni][h * 2 + 1];
                    unsigned b0 = (v0 > THRESH_F && impj[ni][0] >= impi[mi][h]) ? 1u : 0u;
                    unsigned b1 = (v1 > THRESH_F && impj[ni][1] >= impi[mi][h]) ? 1u : 0u;
                    unsigned bits = (b0 << ((ni & 3) * 8 + 2 * t)) | (b1 << ((ni & 3) * 8 + 2 * t + 1));
                    if (ni < 4) w0 |= bits; else w1 |= bits;
                }
                w0 |= __shfl_xor_sync(0xffffffffu, w0, 1);
                w0 |= __shfl_xor_sync(0xffffffffu, w0, 2);
                w1 |= __shfl_xor_sync(0xffffffffu, w1, 1);
                w1 |= __shfl_xor_sync(0xffffffffu, w1, 2);
                if (t == 0) {
                    int r = row0 + wm * 32 + mi * 16 + g + 8 * h;
                    cond[(size_t)r * wstride + (cb >> 5)    ] = w0;
                    cond[(size_t)r * wstride + (cb >> 5) + 1] = w1;
                }
            }
        }
    } else {
        float* C = (float*)Cv + (size_t)z * sC;
        float2 bv[8];
#pragma unroll
        for (int ni = 0; ni < 8; ni++)
            bv[ni] = *(const float2*)(bias + col0 + wn * 64 + ni * 8 + 2 * t);
        float mkr[2][2];
#pragma unroll
        for (int mi = 0; mi < 2; mi++)
#pragma unroll
            for (int h = 0; h < 2; h++)
                mkr[mi][h] = (EPI == EPI_BIAS_MASK)
                           ? rowmask[row0 + wm * 32 + mi * 16 + g + 8 * h] : 1.0f;

#pragma unroll
        for (int mi = 0; mi < 2; mi++) {
#pragma unroll
            for (int ni = 0; ni < 8; ni++) {
                const int c = col0 + wn * 64 + ni * 8 + 2 * t;
#pragma unroll
                for (int h = 0; h < 2; h++) {
                    const int r = row0 + wm * 32 + mi * 16 + g + 8 * h;
                    float v0 = acc[mi][ni][h * 2 + 0] + bv[ni].x;
                    float v1 = acc[mi][ni][h * 2 + 1] + bv[ni].y;
                    if (EPI == EPI_GELU) {
                        v0 = f2tf_f(gelu_exact(v0)); v1 = f2tf_f(gelu_exact(v1));
                    } else {
                        v0 *= mkr[mi][h]; v1 *= mkr[mi][h];
                    }
                    *(float2*)(C + (size_t)r * Ncols + c) = make_float2(v0, v1);
                }
            }
        }
    }
}

// ---------------- prep: RND = tf32(seg), SEGI = tf32(seg*imp) ----------------
__global__ __launch_bounds__(256)
void prep_seg(const float4* __restrict__ seg, const float* __restrict__ imp,
              float4* __restrict__ rnd, float4* __restrict__ segi)
{
    size_t idx = (size_t)blockIdx.x * 256 + threadIdx.x;   // over MROWS*HID/4
    float4 v = seg[idx];
    float s = imp[idx >> 10];                              // HID/4 = 1024 float4 per row
    float4 r, w;
    r.x = f2tf_f(v.x); r.y = f2tf_f(v.y); r.z = f2tf_f(v.z); r.w = f2tf_f(v.w);
    w.x = f2tf_f(v.x * s); w.y = f2tf_f(v.y * s); w.z = f2tf_f(v.z * s); w.w = f2tf_f(v.w * s);
    rnd[idx] = r;
    segi[idx] = w;
}

// ---------------- 32x32 tiled transpose with tf32 rounding ----------------
__global__ void transpose32(const float* __restrict__ in, float* __restrict__ out,
                            int R, int C)
{
    __shared__ float t[32][33];
    const int c0 = blockIdx.x * 32, r0 = blockIdx.y * 32;
#pragma unroll
    for (int j = 0; j < 32; j += 8)
        t[threadIdx.y + j][threadIdx.x] =
            f2tf_f(in[(size_t)(r0 + threadIdx.y + j) * C + c0 + threadIdx.x]);
    __syncthreads();
#pragma unroll
    for (int j = 0; j < 32; j += 8)
        out[(size_t)(c0 + threadIdx.y + j) * R + r0 + threadIdx.x] = t[threadIdx.x][threadIdx.y + j];
}

// ---------------- LayerNorm + L2 normalize (tf32-rounded output) ----------------
__global__ __launch_bounds__(256)
void ln_normalize(const float* __restrict__ P, const float* __restrict__ gw,
                  const float* __restrict__ bw, float* __restrict__ O)
{
    const long long row = blockIdx.x;
    const float4* p4 = (const float4*)(P + row * HALF_K);
    float4*       o4 = (float4*)(O + row * HALF_K);
    const int tid = threadIdx.x, lane = tid & 31, warp = tid >> 5;

    float4 x0 = p4[tid], x1 = p4[tid + 256];
    float s1 = x0.x + x0.y + x0.z + x0.w + x1.x + x1.y + x1.z + x1.w;
    float s2 = x0.x * x0.x + x0.y * x0.y + x0.z * x0.z + x0.w * x0.w
             + x1.x * x1.x + x1.y * x1.y + x1.z * x1.z + x1.w * x1.w;

    __shared__ float shA[8], shB[8];
#pragma unroll
    for (int o = 16; o > 0; o >>= 1) {
        s1 += __shfl_down_sync(0xffffffffu, s1, o);
        s2 += __shfl_down_sync(0xffffffffu, s2, o);
    }
    if (lane == 0) { shA[warp] = s1; shB[warp] = s2; }
    __syncthreads();
    if (tid == 0) {
        float a = 0.f, b = 0.f;
        for (int w = 0; w < 8; w++) { a += shA[w]; b += shB[w]; }
        shA[0] = a; shB[0] = b;
    }
    __syncthreads();
    const float mu   = shA[0] * (1.0f / HALF_K);
    const float var  = shB[0] * (1.0f / HALF_K) - mu * mu;
    const float rstd = rsqrtf(var + 1e-5f);

    float4 gg0 = ((const float4*)gw)[tid], gg1 = ((const float4*)gw)[tid + 256];
    float4 bb0 = ((const float4*)bw)[tid], bb1 = ((const float4*)bw)[tid + 256];

    float4 y0, y1;
    y0.x = (x0.x - mu) * rstd * gg0.x + bb0.x;
    y0.y = (x0.y - mu) * rstd * gg0.y + bb0.y;
    y0.z = (x0.z - mu) * rstd * gg0.z + bb0.z;
    y0.w = (x0.w - mu) * rstd * gg0.w + bb0.w;
    y1.x = (x1.x - mu) * rstd * gg1.x + bb1.x;
    y1.y = (x1.y - mu) * rstd * gg1.y + bb1.y;
    y1.z = (x1.z - mu) * rstd * gg1.z + bb1.z;
    y1.w = (x1.w - mu) * rstd * gg1.w + bb1.w;

    float s3 = y0.x * y0.x + y0.y * y0.y + y0.z * y0.z + y0.w * y0.w
             + y1.x * y1.x + y1.y * y1.y + y1.z * y1.z + y1.w * y1.w;

    __syncthreads();
#pragma unroll
    for (int o = 16; o > 0; o >>= 1) s3 += __shfl_down_sync(0xffffffffu, s3, o);
    if (lane == 0) shA[warp] = s3;
    __syncthreads();
    if (tid == 0) {
        float a = 0.f;
        for (int w = 0; w < 8; w++) a += shA[w];
        shA[0] = a;
    }
    __syncthreads();
    const float inv = 1.0f / (sqrtf(shA[0]) + 1e-8f);

    y0.x = f2tf_f(y0.x * inv); y0.y = f2tf_f(y0.y * inv);
    y0.z = f2tf_f(y0.z * inv); y0.w = f2tf_f(y0.w * inv);
    y1.x = f2tf_f(y1.x * inv); y1.y = f2tf_f(y1.y * inv);
    y1.z = f2tf_f(y1.z * inv); y1.w = f2tf_f(y1.w * inv);
    o4[tid] = y0; o4[tid + 256] = y1;
}

// ---------------- sequential greedy keep (1 warp per batch, depth-16 prefetch) ----------------
__global__ void greedy_keep(const unsigned* __restrict__ cond,
                            float* __restrict__ kept1, float* __restrict__ kept2)
{
    const int warp = threadIdx.x >> 5, lane = threadIdx.x & 31;
    const int b = warp;  // 8 warps = 8 batches
    const unsigned* cw = cond + b * 1024 * 32;

    unsigned ring[16];
#pragma unroll
    for (int d = 0; d < 16; d++) ring[d] = cw[d * 32 + lane];

    unsigned Kr = 0;
    for (int ib = 0; ib < 1024; ib += 16) {
#pragma unroll
        for (int d = 0; d < 16; d++) {
            const int i = ib + d;
            unsigned word = ring[d];
            ring[d] = (i + 16 < 1024) ? cw[(i + 16) * 32 + lane] : 0u;  // prefetch
            const int wHi = i >> 5, bp = i & 31;
            unsigned m = (lane < wHi) ? 0xffffffffu
                       : ((lane == wHi) ? (bp ? ((1u << bp) - 1u) : 0u) : 0u);
            bool sup = __any_sync(0xffffffffu, (word & m & Kr) != 0u);
            if (!sup && lane == wHi) Kr |= (1u << bp);
        }
    }
#pragma unroll
    for (int bpos = 0; bpos < 32; bpos++) {
        float v = (float)((Kr >> bpos) & 1u);
        int j = lane * 32 + bpos;
        kept1[b * 1024 + j] = v;
        kept2[b * 1024 + j] = v;
    }
}

// ---------------- launch ----------------
extern "C" void kernel_launch(void* const* d_in, const int* in_sizes, int n_in,
                              void* d_out, int out_size)
{
    const float* seg  = (const float*)d_in[0];
    const float* imp  = (const float*)d_in[1];
    const float* Wsim = (const float*)d_in[2];
    const float* bsim = (const float*)d_in[3];
    const float* lng  = (const float*)d_in[4];
    const float* lnb  = (const float*)d_in[5];
    const float* Wd1  = (const float*)d_in[6];
    const float* bd1  = (const float*)d_in[7];
    const float* Wd2  = (const float*)d_in[8];
    const float* bd2  = (const float*)d_in[9];
    float* out = (float*)d_out;

    float *P, *NORM, *RND, *SEGI, *WsimT, *Wd1T, *Wd2T, *KEPT; unsigned* COND;
    cudaGetSymbolAddress((void**)&P,     g_P);
    cudaGetSymbolAddress((void**)&NORM,  g_NORM);
    cudaGetSymbolAddress((void**)&RND,   g_RND);
    cudaGetSymbolAddress((void**)&SEGI,  g_SEGI);
    cudaGetSymbolAddress((void**)&WsimT, g_WsimT);
    cudaGetSymbolAddress((void**)&Wd1T,  g_Wd1T);
    cudaGetSymbolAddress((void**)&Wd2T,  g_Wd2T);
    cudaGetSymbolAddress((void**)&COND,  g_COND);
    cudaGetSymbolAddress((void**)&KEPT,  g_KEPT);

    cudaFuncSetAttribute(gemm_sync<EPI_GELU>,      cudaFuncAttributeMaxDynamicSharedMemorySize, SMEM_BYTES);
    cudaFuncSetAttribute(gemm_sync<EPI_BIAS_MASK>, cudaFuncAttributeMaxDynamicSharedMemorySize, SMEM_BYTES);
    cudaFuncSetAttribute(gemm_sync<EPI_PACK>,      cudaFuncAttributeMaxDynamicSharedMemorySize, SMEM_BYTES);

    const dim3 tblk(32, 8);

    // pre-rounded activations + weight transposes (tf32)
    prep_seg<<<(MROWS * (HID / 4)) / 256, 256>>>((const float4*)seg, imp,
                                                 (float4*)RND, (float4*)SEGI);
    transpose32<<<dim3(HALF_K / 32, HID / 32), tblk>>>(Wsim, WsimT, HID, HALF_K);
    transpose32<<<dim3(HALF_K / 32, HID / 32), tblk>>>(Wd1,  Wd1T,  HID, HALF_K);
    transpose32<<<dim3(HID / 32, HALF_K / 32), tblk>>>(Wd2,  Wd2T,  HALF_K, HID);

    // 1) P = tf32(gelu(RND @ W_sim + b_sim))
    gemm_sync<EPI_GELU><<<dim3(HALF_K / BN, MROWS / BM, 1), NTHREADS, SMEM_BYTES>>>(
        RND, WsimT, P, MROWS, HALF_K, HID, bsim, nullptr, nullptr, 0, 0, 0);

    // 2) NORM = tf32(l2norm(layernorm(P)))
    ln_normalize<<<MROWS, 256>>>(P, lng, lnb, NORM);

    // 3) sim = NORM @ NORM^T with fused threshold/importance bit-pack
    gemm_sync<EPI_PACK><<<dim3(N_SEQ / BN, N_SEQ / BM, B_BATCH), NTHREADS, SMEM_BYTES>>>(
        NORM, NORM, COND, N_SEQ, N_SEQ, HALF_K, nullptr, nullptr, imp,
        (long long)N_SEQ * HALF_K, (long long)N_SEQ * HALF_K, (long long)N_SEQ * (N_SEQ / 32));

    // 4) sequential greedy keep -> KEPT + kept_mask output region
    greedy_keep<<<1, 256>>>(COND, KEPT, out + (size_t)MROWS * HID);

    // 5) H = tf32(gelu(SEGI @ W_d1 + b_d1))   (reuse P as H)
    gemm_sync<EPI_GELU><<<dim3(HALF_K / BN, MROWS / BM, 1), NTHREADS, SMEM_BYTES>>>(
        SEGI, Wd1T, P, MROWS, HALF_K, HID, bd1, nullptr, nullptr, 0, 0, 0);

    // 6) out = (H @ W_d2 + b_d2) * kept
    gemm_sync<EPI_BIAS_MASK><<<dim3(HID / BN, MROWS / BM, 1), NTHREADS, SMEM_BYTES>>>(
        P, Wd2T, out, MROWS, HID, HALF_K, bd2, KEPT, nullptr, 0, 0, 0);
}